// round 1
// baseline (speedup 1.0000x reference)
#include <cuda_runtime.h>
#include <math.h>

#define BATCH 2
#define SEQ   2048
#define DIM   2048
#define NH    16
#define NKV   8
#define HD    128
#define KVD   (NKV*HD)
#define SK    64
#define INV_SQRT_HD 0.08838834764831845f  /* 1/sqrt(128) */

/* ------------------------- scratch (static device) ------------------------ */
__device__ float g_ASq[(size_t)BATCH*SEQ*SK];
__device__ float g_ASk[(size_t)BATCH*SEQ*SK];
__device__ float g_ASv[(size_t)BATCH*SEQ*SK];
__device__ float g_ASo[(size_t)BATCH*SEQ*SK];
__device__ float g_Tq [(size_t)BATCH*DIM*SK];
__device__ float g_Tk [(size_t)BATCH*KVD*SK];
__device__ float g_Tv [(size_t)BATCH*KVD*SK];
__device__ float g_To [(size_t)BATCH*DIM*SK];
__device__ float g_q  [(size_t)BATCH*NH *SEQ*HD];
__device__ float g_k  [(size_t)BATCH*NKV*SEQ*HD];
__device__ float g_v  [(size_t)BATCH*NKV*SEQ*HD];
__device__ float g_ao [(size_t)BATCH*SEQ*DIM];

/* =====================================================================
 * k_gemm: 64x64 tile of C = alpha * A(MxK,row) * B(Kx64,row)
 *   mode 0: AS_{q,k,v}  = x @ S / 64           grid (32, 3, B)
 *   mode 1: T_{q,k,v,o} = w @ S                grid (32, 4, B)
 *   mode 2: AS_o        = attn_out @ So / 64   grid (32, 1, B)
 * =====================================================================*/
__global__ __launch_bounds__(256) void k_gemm(
    const float* __restrict__ x,
    const float* __restrict__ Sq, const float* __restrict__ Sk,
    const float* __restrict__ Sv, const float* __restrict__ So,
    const float* __restrict__ wq, const float* __restrict__ wk,
    const float* __restrict__ wv, const float* __restrict__ wo,
    int mode)
{
    int b = blockIdx.z, which = blockIdx.y;
    int m0 = blockIdx.x * 64;
    const float* A; const float* Bm; float* C; float alpha;
    const int K = DIM;

    if (mode == 0) {
        A  = x + (size_t)b*SEQ*DIM;
        Bm = (which==0 ? Sq : which==1 ? Sk : Sv) + (size_t)b*DIM*SK;
        C  = (which==0 ? g_ASq : which==1 ? g_ASk : g_ASv) + (size_t)b*SEQ*SK;
        alpha = 1.0f/SK;
    } else if (mode == 1) {
        int M = (which==0 || which==3) ? DIM : KVD;
        if (m0 >= M) return;
        A  = (which==0 ? wq : which==1 ? wk : which==2 ? wv : wo);
        Bm = (which==0 ? Sq : which==1 ? Sk : which==2 ? Sv : So) + (size_t)b*DIM*SK;
        C  = (which==0 ? g_Tq + (size_t)b*DIM*SK :
              which==1 ? g_Tk + (size_t)b*KVD*SK :
              which==2 ? g_Tv + (size_t)b*KVD*SK :
                         g_To + (size_t)b*DIM*SK);
        alpha = 1.0f;
    } else {
        A  = g_ao + (size_t)b*SEQ*DIM;
        Bm = So   + (size_t)b*DIM*SK;
        C  = g_ASo + (size_t)b*SEQ*SK;
        alpha = 1.0f/SK;
    }
    A += (size_t)m0 * K;

    __shared__ float sA[16][68];   /* transposed: [k][m], pad 68 -> aligned f4 */
    __shared__ float sB[16][64];   /* natural:    [k][n] */

    int tid = threadIdx.x;
    int tx = tid & 15, ty = tid >> 4;
    int la_r = tid >> 2,  la_c = (tid & 3)  * 4;
    int lb_r = tid >> 4,  lb_c = (tid & 15) * 4;

    float acc[4][4] = {};

    for (int k0 = 0; k0 < K; k0 += 16) {
        float4 av = *(const float4*)(A  + (size_t)la_r * K + k0 + la_c);
        float4 bv = *(const float4*)(Bm + (size_t)(k0 + lb_r) * SK + lb_c);
        __syncthreads();
        sA[la_c+0][la_r] = av.x; sA[la_c+1][la_r] = av.y;
        sA[la_c+2][la_r] = av.z; sA[la_c+3][la_r] = av.w;
        *(float4*)&sB[lb_r][lb_c] = bv;
        __syncthreads();
        #pragma unroll
        for (int kk = 0; kk < 16; kk++) {
            float4 a  = *(const float4*)&sA[kk][ty*4];
            float4 bb = *(const float4*)&sB[kk][tx*4];
            acc[0][0]+=a.x*bb.x; acc[0][1]+=a.x*bb.y; acc[0][2]+=a.x*bb.z; acc[0][3]+=a.x*bb.w;
            acc[1][0]+=a.y*bb.x; acc[1][1]+=a.y*bb.y; acc[1][2]+=a.y*bb.z; acc[1][3]+=a.y*bb.w;
            acc[2][0]+=a.z*bb.x; acc[2][1]+=a.z*bb.y; acc[2][2]+=a.z*bb.z; acc[2][3]+=a.z*bb.w;
            acc[3][0]+=a.w*bb.x; acc[3][1]+=a.w*bb.y; acc[3][2]+=a.w*bb.z; acc[3][3]+=a.w*bb.w;
        }
    }
    #pragma unroll
    for (int i = 0; i < 4; i++) {
        float4 o = make_float4(acc[i][0]*alpha, acc[i][1]*alpha,
                               acc[i][2]*alpha, acc[i][3]*alpha);
        *(float4*)(C + (size_t)(m0 + ty*4 + i) * SK + tx*4) = o;
    }
}

/* =====================================================================
 * k_proj: 64x64 tile of  X = AS (Sx64) @ T^T (64xM)   (K = 64)
 * then per-mode epilogue:
 *   mode 0: RoPE, write g_q  [b,h,s,d]      grid (32, 32, B)
 *   mode 1: RoPE, write g_k  [b,kvh,s,d]    grid (32, 16, B)
 *   mode 2:       write g_v  [b,kvh,s,d]    grid (32, 16, B)
 *   mode 3:       write d_out[b,s,m]        grid (32, 32, B)
 * =====================================================================*/
__global__ __launch_bounds__(256) void k_proj(const float* __restrict__ freqs,
                                              float* __restrict__ dout, int mode)
{
    int b  = blockIdx.z;
    int s0 = blockIdx.x * 64, m0 = blockIdx.y * 64;

    const float* ASp; const float* Tp;
    if      (mode == 0) { ASp = g_ASq + (size_t)b*SEQ*SK; Tp = g_Tq + (size_t)b*DIM*SK; }
    else if (mode == 1) { ASp = g_ASk + (size_t)b*SEQ*SK; Tp = g_Tk + (size_t)b*KVD*SK; }
    else if (mode == 2) { ASp = g_ASv + (size_t)b*SEQ*SK; Tp = g_Tv + (size_t)b*KVD*SK; }
    else                { ASp = g_ASo + (size_t)b*SEQ*SK; Tp = g_To + (size_t)b*DIM*SK; }

    __shared__ float sA[64][68];   /* [k][srow] */
    __shared__ float sB[64][68];   /* [k][mrow] */

    int tid = threadIdx.x, tx = tid & 15, ty = tid >> 4;

    #pragma unroll
    for (int it = 0; it < 4; it++) {
        int r  = (tid >> 4) + it*16;
        int c4 = (tid & 15) * 4;
        float4 a = *(const float4*)(ASp + (size_t)(s0 + r)*SK + c4);
        sA[c4+0][r]=a.x; sA[c4+1][r]=a.y; sA[c4+2][r]=a.z; sA[c4+3][r]=a.w;
        float4 t = *(const float4*)(Tp  + (size_t)(m0 + r)*SK + c4);
        sB[c4+0][r]=t.x; sB[c4+1][r]=t.y; sB[c4+2][r]=t.z; sB[c4+3][r]=t.w;
    }
    __syncthreads();

    float acc[4][4] = {};
    #pragma unroll
    for (int k = 0; k < 64; k++) {
        float4 a  = *(const float4*)&sA[k][ty*4];
        float4 bb = *(const float4*)&sB[k][tx*4];
        acc[0][0]+=a.x*bb.x; acc[0][1]+=a.x*bb.y; acc[0][2]+=a.x*bb.z; acc[0][3]+=a.x*bb.w;
        acc[1][0]+=a.y*bb.x; acc[1][1]+=a.y*bb.y; acc[1][2]+=a.y*bb.z; acc[1][3]+=a.y*bb.w;
        acc[2][0]+=a.z*bb.x; acc[2][1]+=a.z*bb.y; acc[2][2]+=a.z*bb.z; acc[2][3]+=a.z*bb.w;
        acc[3][0]+=a.w*bb.x; acc[3][1]+=a.w*bb.y; acc[3][2]+=a.w*bb.z; acc[3][3]+=a.w*bb.w;
    }

    if (mode == 3) {
        #pragma unroll
        for (int i = 0; i < 4; i++) {
            *(float4*)(dout + ((size_t)b*SEQ + s0 + ty*4 + i)*DIM + m0 + tx*4) =
                make_float4(acc[i][0], acc[i][1], acc[i][2], acc[i][3]);
        }
    } else if (mode == 2) {
        int h  = m0 >> 7;
        int d0 = (m0 & 127) + tx*4;
        float* base = g_v + ((size_t)(b*NKV + h))*SEQ*HD;
        #pragma unroll
        for (int i = 0; i < 4; i++) {
            *(float4*)(base + (size_t)(s0 + ty*4 + i)*HD + d0) =
                make_float4(acc[i][0], acc[i][1], acc[i][2], acc[i][3]);
        }
    } else {
        int h  = m0 >> 7;
        int d0 = (m0 & 127) + tx*4;
        int dh = d0 >> 1;
        float* base = (mode == 0) ? g_q + ((size_t)(b*NH  + h))*SEQ*HD
                                  : g_k + ((size_t)(b*NKV + h))*SEQ*HD;
        #pragma unroll
        for (int i = 0; i < 4; i++) {
            int srow = s0 + ty*4 + i;
            const float* f = freqs + ((size_t)srow*64 + dh)*2;
            float c0 = f[0], n0 = f[1], c1 = f[2], n1 = f[3];
            /* out_even = x0*sin - x1*cos ; out_odd = x0*cos + x1*sin */
            float e0 = acc[i][0]*n0 - acc[i][1]*c0;
            float o0 = acc[i][0]*c0 + acc[i][1]*n0;
            float e1 = acc[i][2]*n1 - acc[i][3]*c1;
            float o1 = acc[i][2]*c1 + acc[i][3]*n1;
            *(float4*)(base + (size_t)srow*HD + d0) = make_float4(e0, o0, e1, o1);
        }
    }
}

/* =====================================================================
 * k_flash: causal flash attention, fp32.
 *   BM=BN=64, D=128, 256 threads (16x16), S micro 4x4, O micro 4x8.
 *   grid (SEQ/64, NH, B). GQA: kv head = h/2. Scale folded into Q load.
 * =====================================================================*/
#define FLASH_SMEM ((2*128*68 + 64*132 + 64*65) * 4)

__global__ __launch_bounds__(256) void k_flash()
{
    extern __shared__ float sm[];
    float (*sQ)[68]  = (float (*)[68])  sm;                       /* [d][r] */
    float (*sK)[68]  = (float (*)[68]) (sm + 128*68);             /* [d][c] */
    float (*sV)[132] = (float (*)[132])(sm + 2*128*68);           /* [p][c] */
    float (*sP)[65]  = (float (*)[65]) (sm + 2*128*68 + 64*132);  /* [r][p] */

    int tid = threadIdx.x, tx = tid & 15, ty = tid >> 4;
    int qt = blockIdx.x, h = blockIdx.y, b = blockIdx.z;

    const float* Qg    = g_q + ((size_t)(b*NH  + h))     *SEQ*HD + (size_t)qt*64*HD;
    const float* Kbase = g_k + ((size_t)(b*NKV + (h>>1)))*SEQ*HD;
    const float* Vbase = g_v + ((size_t)(b*NKV + (h>>1)))*SEQ*HD;

    #pragma unroll
    for (int it = 0; it < 8; it++) {
        int slot = tid + it*256;
        int r = slot >> 5, c4 = (slot & 31) * 4;
        float4 v = *(const float4*)(Qg + (size_t)r*HD + c4);
        sQ[c4+0][r] = v.x*INV_SQRT_HD; sQ[c4+1][r] = v.y*INV_SQRT_HD;
        sQ[c4+2][r] = v.z*INV_SQRT_HD; sQ[c4+3][r] = v.w*INV_SQRT_HD;
    }

    float acc[4][8] = {};
    float mi[4] = {-1e30f, -1e30f, -1e30f, -1e30f};
    float li[4] = {0.f, 0.f, 0.f, 0.f};

    for (int kt = 0; kt <= qt; kt++) {
        const float* Kg = Kbase + (size_t)kt*64*HD;
        const float* Vg = Vbase + (size_t)kt*64*HD;
        #pragma unroll
        for (int it = 0; it < 8; it++) {
            int slot = tid + it*256;
            int r = slot >> 5, c4 = (slot & 31) * 4;
            float4 kv = *(const float4*)(Kg + (size_t)r*HD + c4);
            sK[c4+0][r]=kv.x; sK[c4+1][r]=kv.y; sK[c4+2][r]=kv.z; sK[c4+3][r]=kv.w;
            float4 vv = *(const float4*)(Vg + (size_t)r*HD + c4);
            *(float4*)&sV[r][c4] = vv;
        }
        __syncthreads();

        /* S = (Q*scale) K^T */
        float s[4][4] = {};
        #pragma unroll 16
        for (int d = 0; d < 128; d++) {
            float4 a  = *(const float4*)&sQ[d][ty*4];
            float4 k4 = *(const float4*)&sK[d][tx*4];
            s[0][0]+=a.x*k4.x; s[0][1]+=a.x*k4.y; s[0][2]+=a.x*k4.z; s[0][3]+=a.x*k4.w;
            s[1][0]+=a.y*k4.x; s[1][1]+=a.y*k4.y; s[1][2]+=a.y*k4.z; s[1][3]+=a.y*k4.w;
            s[2][0]+=a.z*k4.x; s[2][1]+=a.z*k4.y; s[2][2]+=a.z*k4.z; s[2][3]+=a.z*k4.w;
            s[3][0]+=a.w*k4.x; s[3][1]+=a.w*k4.y; s[3][2]+=a.w*k4.z; s[3][3]+=a.w*k4.w;
        }

        if (kt == qt) {   /* diagonal tile: causal mask */
            #pragma unroll
            for (int i = 0; i < 4; i++)
                #pragma unroll
                for (int j = 0; j < 4; j++)
                    if (tx*4 + j > ty*4 + i) s[i][j] = -1e30f;
        }

        /* online softmax */
        #pragma unroll
        for (int i = 0; i < 4; i++) {
            float tm = fmaxf(fmaxf(s[i][0], s[i][1]), fmaxf(s[i][2], s[i][3]));
            tm = fmaxf(tm, __shfl_xor_sync(0xffffffffu, tm, 1));
            tm = fmaxf(tm, __shfl_xor_sync(0xffffffffu, tm, 2));
            tm = fmaxf(tm, __shfl_xor_sync(0xffffffffu, tm, 4));
            tm = fmaxf(tm, __shfl_xor_sync(0xffffffffu, tm, 8));
            float newm = fmaxf(mi[i], tm);
            float al   = __expf(mi[i] - newm);
            s[i][0] = __expf(s[i][0] - newm);
            s[i][1] = __expf(s[i][1] - newm);
            s[i][2] = __expf(s[i][2] - newm);
            s[i][3] = __expf(s[i][3] - newm);
            float rs = s[i][0] + s[i][1] + s[i][2] + s[i][3];
            rs += __shfl_xor_sync(0xffffffffu, rs, 1);
            rs += __shfl_xor_sync(0xffffffffu, rs, 2);
            rs += __shfl_xor_sync(0xffffffffu, rs, 4);
            rs += __shfl_xor_sync(0xffffffffu, rs, 8);
            li[i] = li[i]*al + rs;
            mi[i] = newm;
            #pragma unroll
            for (int c = 0; c < 8; c++) acc[i][c] *= al;
            sP[ty*4+i][tx*4+0] = s[i][0];
            sP[ty*4+i][tx*4+1] = s[i][1];
            sP[ty*4+i][tx*4+2] = s[i][2];
            sP[ty*4+i][tx*4+3] = s[i][3];
        }
        __syncthreads();

        /* O += P V */
        #pragma unroll 8
        for (int p = 0; p < 64; p++) {
            float b0 = sP[ty*4+0][p], b1 = sP[ty*4+1][p];
            float b2 = sP[ty*4+2][p], b3 = sP[ty*4+3][p];
            float4 v0 = *(const float4*)&sV[p][tx*8];
            float4 v1 = *(const float4*)&sV[p][tx*8 + 4];
            acc[0][0]+=b0*v0.x; acc[0][1]+=b0*v0.y; acc[0][2]+=b0*v0.z; acc[0][3]+=b0*v0.w;
            acc[0][4]+=b0*v1.x; acc[0][5]+=b0*v1.y; acc[0][6]+=b0*v1.z; acc[0][7]+=b0*v1.w;
            acc[1][0]+=b1*v0.x; acc[1][1]+=b1*v0.y; acc[1][2]+=b1*v0.z; acc[1][3]+=b1*v0.w;
            acc[1][4]+=b1*v1.x; acc[1][5]+=b1*v1.y; acc[1][6]+=b1*v1.z; acc[1][7]+=b1*v1.w;
            acc[2][0]+=b2*v0.x; acc[2][1]+=b2*v0.y; acc[2][2]+=b2*v0.z; acc[2][3]+=b2*v0.w;
            acc[2][4]+=b2*v1.x; acc[2][5]+=b2*v1.y; acc[2][6]+=b2*v1.z; acc[2][7]+=b2*v1.w;
            acc[3][0]+=b3*v0.x; acc[3][1]+=b3*v0.y; acc[3][2]+=b3*v0.z; acc[3][3]+=b3*v0.w;
            acc[3][4]+=b3*v1.x; acc[3][5]+=b3*v1.y; acc[3][6]+=b3*v1.z; acc[3][7]+=b3*v1.w;
        }
        __syncthreads();
    }

    float* Og = g_ao + ((size_t)b*SEQ + (size_t)qt*64)*DIM + (size_t)h*HD;
    #pragma unroll
    for (int i = 0; i < 4; i++) {
        float inv = 1.0f / li[i];
        int r = ty*4 + i;
        *(float4*)(Og + (size_t)r*DIM + tx*8) =
            make_float4(acc[i][0]*inv, acc[i][1]*inv, acc[i][2]*inv, acc[i][3]*inv);
        *(float4*)(Og + (size_t)r*DIM + tx*8 + 4) =
            make_float4(acc[i][4]*inv, acc[i][5]*inv, acc[i][6]*inv, acc[i][7]*inv);
    }
}

/* ========================= launch ========================= */
extern "C" void kernel_launch(void* const* d_in, const int* in_sizes, int n_in,
                              void* d_out, int out_size)
{
    const float* x  = (const float*)d_in[0];
    const float* wq = (const float*)d_in[1];
    const float* wk = (const float*)d_in[2];
    const float* wv = (const float*)d_in[3];
    const float* wo = (const float*)d_in[4];
    const float* Sq = (const float*)d_in[5];
    const float* Sk = (const float*)d_in[6];
    const float* Sv = (const float*)d_in[7];
    const float* So = (const float*)d_in[8];
    const float* fr = (const float*)d_in[9];
    float* out = (float*)d_out;

    cudaFuncSetAttribute(k_flash, cudaFuncAttributeMaxDynamicSharedMemorySize,
                         FLASH_SMEM);

    dim3 blk(256);
    /* AS_{q,k,v} = x @ S / 64 */
    k_gemm<<<dim3(32, 3, BATCH), blk>>>(x, Sq, Sk, Sv, So, wq, wk, wv, wo, 0);
    /* T_{q,k,v,o} = w @ S */
    k_gemm<<<dim3(32, 4, BATCH), blk>>>(x, Sq, Sk, Sv, So, wq, wk, wv, wo, 1);
    /* q/k/v projections (+RoPE, layout to [b,h,s,d]) */
    k_proj<<<dim3(32, 32, BATCH), blk>>>(fr, out, 0);
    k_proj<<<dim3(32, 16, BATCH), blk>>>(fr, out, 1);
    k_proj<<<dim3(32, 16, BATCH), blk>>>(fr, out, 2);
    /* causal flash attention -> g_ao [b,s,DIM] */
    k_flash<<<dim3(32, NH, BATCH), blk, FLASH_SMEM>>>();
    /* AS_o = attn_out @ So / 64 */
    k_gemm<<<dim3(32, 1, BATCH), blk>>>(x, Sq, Sk, Sv, So, wq, wk, wv, wo, 2);
    /* final = AS_o @ To^T -> d_out */
    k_proj<<<dim3(32, 32, BATCH), blk>>>(fr, out, 3);
}

// round 3
// speedup vs baseline: 1.2318x; 1.2318x over previous
#include <cuda_runtime.h>
#include <math.h>
#include <stdint.h>

#define BATCH 2
#define SEQ   2048
#define DIM   2048
#define NH    16
#define NKV   8
#define HD    128
#define KVD   (NKV*HD)
#define SK    64
#define INV_SQRT_HD 0.08838834764831845f  /* 1/sqrt(128) */

/* ------------------------- scratch (static device) ------------------------ */
__device__ float g_ASq[(size_t)BATCH*SEQ*SK];
__device__ float g_ASk[(size_t)BATCH*SEQ*SK];
__device__ float g_ASv[(size_t)BATCH*SEQ*SK];
__device__ float g_ASo[(size_t)BATCH*SEQ*SK];
__device__ float g_Tq [(size_t)BATCH*DIM*SK];
__device__ float g_Tk [(size_t)BATCH*KVD*SK];
__device__ float g_Tv [(size_t)BATCH*KVD*SK];
__device__ float g_To [(size_t)BATCH*DIM*SK];
__device__ float g_q  [(size_t)BATCH*NH *SEQ*HD];
__device__ float g_k  [(size_t)BATCH*NKV*SEQ*HD];
__device__ float g_v  [(size_t)BATCH*NKV*SEQ*HD];
__device__ float g_ao [(size_t)BATCH*SEQ*DIM];

/* ---------------------- tf32 / mma helpers ---------------------- */
__device__ __forceinline__ uint32_t f2tf32(float f) {
    uint32_t u;
    asm("cvt.rna.tf32.f32 %0, %1;" : "=r"(u) : "f"(f));
    return u;
}
__device__ __forceinline__ float f2tf32f(float f) {
    return __uint_as_float(f2tf32(f));
}
/* 3xTF32 split: f = hi + lo with ~21 effective mantissa bits */
__device__ __forceinline__ void split_tf32(float f, uint32_t& hi, uint32_t& lo) {
    float h = f2tf32f(f);
    hi = __float_as_uint(h);
    lo = f2tf32(f - h);
}
__device__ __forceinline__ void mma_tf32(float* c, const uint32_t* a,
                                         uint32_t b0, uint32_t b1) {
    asm volatile(
        "mma.sync.aligned.m16n8k8.row.col.f32.tf32.tf32.f32 "
        "{%0,%1,%2,%3}, {%4,%5,%6,%7}, {%8,%9}, {%0,%1,%2,%3};"
        : "+f"(c[0]), "+f"(c[1]), "+f"(c[2]), "+f"(c[3])
        : "r"(a[0]), "r"(a[1]), "r"(a[2]), "r"(a[3]), "r"(b0), "r"(b1));
}
__device__ __forceinline__ void mma3(float* c,
                                     const uint32_t* ahi, const uint32_t* alo,
                                     uint32_t bh0, uint32_t bh1,
                                     uint32_t bl0, uint32_t bl1) {
    mma_tf32(c, alo, bh0, bh1);   /* small terms first */
    mma_tf32(c, ahi, bl0, bl1);
    mma_tf32(c, ahi, bh0, bh1);
}

/* =====================================================================
 * k_gemm: 64x64 tile of C = alpha * A(MxK,row) * B(Kx64,row)  (fp32)
 * =====================================================================*/
__global__ __launch_bounds__(256) void k_gemm(
    const float* __restrict__ x,
    const float* __restrict__ Sq, const float* __restrict__ Sk,
    const float* __restrict__ Sv, const float* __restrict__ So,
    const float* __restrict__ wq, const float* __restrict__ wk,
    const float* __restrict__ wv, const float* __restrict__ wo,
    int mode)
{
    int b = blockIdx.z, which = blockIdx.y;
    int m0 = blockIdx.x * 64;
    const float* A; const float* Bm; float* C; float alpha;
    const int K = DIM;

    if (mode == 0) {
        A  = x + (size_t)b*SEQ*DIM;
        Bm = (which==0 ? Sq : which==1 ? Sk : Sv) + (size_t)b*DIM*SK;
        C  = (which==0 ? g_ASq : which==1 ? g_ASk : g_ASv) + (size_t)b*SEQ*SK;
        alpha = 1.0f/SK;
    } else if (mode == 1) {
        int M = (which==0 || which==3) ? DIM : KVD;
        if (m0 >= M) return;
        A  = (which==0 ? wq : which==1 ? wk : which==2 ? wv : wo);
        Bm = (which==0 ? Sq : which==1 ? Sk : which==2 ? Sv : So) + (size_t)b*DIM*SK;
        C  = (which==0 ? g_Tq + (size_t)b*DIM*SK :
              which==1 ? g_Tk + (size_t)b*KVD*SK :
              which==2 ? g_Tv + (size_t)b*KVD*SK :
                         g_To + (size_t)b*DIM*SK);
        alpha = 1.0f;
    } else {
        A  = g_ao + (size_t)b*SEQ*DIM;
        Bm = So   + (size_t)b*DIM*SK;
        C  = g_ASo + (size_t)b*SEQ*SK;
        alpha = 1.0f/SK;
    }
    A += (size_t)m0 * K;

    __shared__ float sA[16][68];
    __shared__ float sB[16][64];

    int tid = threadIdx.x;
    int tx = tid & 15, ty = tid >> 4;
    int la_r = tid >> 2,  la_c = (tid & 3)  * 4;
    int lb_r = tid >> 4,  lb_c = (tid & 15) * 4;

    float acc[4][4] = {};

    for (int k0 = 0; k0 < K; k0 += 16) {
        float4 av = *(const float4*)(A  + (size_t)la_r * K + k0 + la_c);
        float4 bv = *(const float4*)(Bm + (size_t)(k0 + lb_r) * SK + lb_c);
        __syncthreads();
        sA[la_c+0][la_r] = av.x; sA[la_c+1][la_r] = av.y;
        sA[la_c+2][la_r] = av.z; sA[la_c+3][la_r] = av.w;
        *(float4*)&sB[lb_r][lb_c] = bv;
        __syncthreads();
        #pragma unroll
        for (int kk = 0; kk < 16; kk++) {
            float4 a  = *(const float4*)&sA[kk][ty*4];
            float4 bb = *(const float4*)&sB[kk][tx*4];
            acc[0][0]+=a.x*bb.x; acc[0][1]+=a.x*bb.y; acc[0][2]+=a.x*bb.z; acc[0][3]+=a.x*bb.w;
            acc[1][0]+=a.y*bb.x; acc[1][1]+=a.y*bb.y; acc[1][2]+=a.y*bb.z; acc[1][3]+=a.y*bb.w;
            acc[2][0]+=a.z*bb.x; acc[2][1]+=a.z*bb.y; acc[2][2]+=a.z*bb.z; acc[2][3]+=a.z*bb.w;
            acc[3][0]+=a.w*bb.x; acc[3][1]+=a.w*bb.y; acc[3][2]+=a.w*bb.z; acc[3][3]+=a.w*bb.w;
        }
    }
    #pragma unroll
    for (int i = 0; i < 4; i++) {
        float4 o = make_float4(acc[i][0]*alpha, acc[i][1]*alpha,
                               acc[i][2]*alpha, acc[i][3]*alpha);
        *(float4*)(C + (size_t)(m0 + ty*4 + i) * SK + tx*4) = o;
    }
}

/* =====================================================================
 * k_proj: 64x64 tile of  X = AS (Sx64) @ T^T (64xM)   (K = 64, fp32)
 * =====================================================================*/
__global__ __launch_bounds__(256) void k_proj(const float* __restrict__ freqs,
                                              float* __restrict__ dout, int mode)
{
    int b  = blockIdx.z;
    int s0 = blockIdx.x * 64, m0 = blockIdx.y * 64;

    const float* ASp; const float* Tp;
    if      (mode == 0) { ASp = g_ASq + (size_t)b*SEQ*SK; Tp = g_Tq + (size_t)b*DIM*SK; }
    else if (mode == 1) { ASp = g_ASk + (size_t)b*SEQ*SK; Tp = g_Tk + (size_t)b*KVD*SK; }
    else if (mode == 2) { ASp = g_ASv + (size_t)b*SEQ*SK; Tp = g_Tv + (size_t)b*KVD*SK; }
    else                { ASp = g_ASo + (size_t)b*SEQ*SK; Tp = g_To + (size_t)b*DIM*SK; }

    __shared__ float sA[64][68];
    __shared__ float sB[64][68];

    int tid = threadIdx.x, tx = tid & 15, ty = tid >> 4;

    #pragma unroll
    for (int it = 0; it < 4; it++) {
        int r  = (tid >> 4) + it*16;
        int c4 = (tid & 15) * 4;
        float4 a = *(const float4*)(ASp + (size_t)(s0 + r)*SK + c4);
        sA[c4+0][r]=a.x; sA[c4+1][r]=a.y; sA[c4+2][r]=a.z; sA[c4+3][r]=a.w;
        float4 t = *(const float4*)(Tp  + (size_t)(m0 + r)*SK + c4);
        sB[c4+0][r]=t.x; sB[c4+1][r]=t.y; sB[c4+2][r]=t.z; sB[c4+3][r]=t.w;
    }
    __syncthreads();

    float acc[4][4] = {};
    #pragma unroll
    for (int k = 0; k < 64; k++) {
        float4 a  = *(const float4*)&sA[k][ty*4];
        float4 bb = *(const float4*)&sB[k][tx*4];
        acc[0][0]+=a.x*bb.x; acc[0][1]+=a.x*bb.y; acc[0][2]+=a.x*bb.z; acc[0][3]+=a.x*bb.w;
        acc[1][0]+=a.y*bb.x; acc[1][1]+=a.y*bb.y; acc[1][2]+=a.y*bb.z; acc[1][3]+=a.y*bb.w;
        acc[2][0]+=a.z*bb.x; acc[2][1]+=a.z*bb.y; acc[2][2]+=a.z*bb.z; acc[2][3]+=a.z*bb.w;
        acc[3][0]+=a.w*bb.x; acc[3][1]+=a.w*bb.y; acc[3][2]+=a.w*bb.z; acc[3][3]+=a.w*bb.w;
    }

    if (mode == 3) {
        #pragma unroll
        for (int i = 0; i < 4; i++) {
            *(float4*)(dout + ((size_t)b*SEQ + s0 + ty*4 + i)*DIM + m0 + tx*4) =
                make_float4(acc[i][0], acc[i][1], acc[i][2], acc[i][3]);
        }
    } else if (mode == 2) {
        int h  = m0 >> 7;
        int d0 = (m0 & 127) + tx*4;
        float* base = g_v + ((size_t)(b*NKV + h))*SEQ*HD;
        #pragma unroll
        for (int i = 0; i < 4; i++) {
            *(float4*)(base + (size_t)(s0 + ty*4 + i)*HD + d0) =
                make_float4(acc[i][0], acc[i][1], acc[i][2], acc[i][3]);
        }
    } else {
        int h  = m0 >> 7;
        int d0 = (m0 & 127) + tx*4;
        int dh = d0 >> 1;
        float* base = (mode == 0) ? g_q + ((size_t)(b*NH  + h))*SEQ*HD
                                  : g_k + ((size_t)(b*NKV + h))*SEQ*HD;
        #pragma unroll
        for (int i = 0; i < 4; i++) {
            int srow = s0 + ty*4 + i;
            const float* f = freqs + ((size_t)srow*64 + dh)*2;
            float c0 = f[0], n0 = f[1], c1 = f[2], n1 = f[3];
            float e0 = acc[i][0]*n0 - acc[i][1]*c0;
            float o0 = acc[i][0]*c0 + acc[i][1]*n0;
            float e1 = acc[i][2]*n1 - acc[i][3]*c1;
            float o1 = acc[i][2]*c1 + acc[i][3]*n1;
            *(float4*)(base + (size_t)srow*HD + d0) = make_float4(e0, o0, e1, o1);
        }
    }
}

/* =====================================================================
 * k_flash: causal flash attention via 3xTF32 mma.sync (fp32-accurate).
 *   BM=128, BN=64, 8 warps, warp-local softmax (16 rows/warp).
 *   Smem holds raw fp32 Q/K/V/P; hi/lo tf32 splits computed in regs
 *   at fragment load. Each scalar product = 3 MMAs (lo*hi, hi*lo, hi*hi).
 *   grid (SEQ/128, NH, B); GQA kv head = h>>1; tail-first scheduling.
 * =====================================================================*/
#define Q_STRIDE  132
#define K_STRIDE  132
#define V_STRIDE  68
#define P_STRIDE  68
#define SQ_OFF    0
#define SK_OFF    (128*Q_STRIDE)
#define SV_OFF    (SK_OFF + 64*K_STRIDE)
#define SP_OFF    (SV_OFF + 128*V_STRIDE)
#define FLASH_SMEM ((SP_OFF + 128*P_STRIDE) * 4)

__global__ void __launch_bounds__(256, 1) k_flash()
{
    extern __shared__ float sm[];
    float* sQ = sm + SQ_OFF;   /* [m][d] fp32 */
    float* sK = sm + SK_OFF;   /* [n][d] fp32 */
    float* sV = sm + SV_OFF;   /* [d][p] fp32 (transposed) */
    float* sP = sm + SP_OFF;   /* [m][p] fp32 */

    int tid = threadIdx.x, lane = tid & 31, w = tid >> 5;
    int qt = (int)gridDim.x - 1 - (int)blockIdx.x;     /* heavy tiles first */
    int h = blockIdx.y, b = blockIdx.z;
    int gid = lane >> 2, qd = lane & 3;

    const float* Qg = g_q + ((size_t)(b*NH  + h))     *SEQ*HD + (size_t)qt*128*HD;
    const float* Kb = g_k + ((size_t)(b*NKV + (h>>1)))*SEQ*HD;
    const float* Vb = g_v + ((size_t)(b*NKV + (h>>1)))*SEQ*HD;

    /* ---- load Q tile (scaled fp32) ---- */
    #pragma unroll
    for (int it = 0; it < 16; it++) {
        int slot = tid + it*256;
        int r = slot >> 5, c4 = (slot & 31) * 4;
        float4 v = *(const float4*)(Qg + (size_t)r*HD + c4);
        float* d = sQ + (size_t)r*Q_STRIDE + c4;
        d[0] = v.x*INV_SQRT_HD; d[1] = v.y*INV_SQRT_HD;
        d[2] = v.z*INV_SQRT_HD; d[3] = v.w*INV_SQRT_HD;
    }
    __syncthreads();

    int m0 = w*16;
    float o[16][4] = {};
    float miA = -1e30f, miB = -1e30f, liA = 0.f, liB = 0.f;
    int row_min = qt*128 + w*16;
    int row_max = row_min + 15;
    int nkt = 2*qt + 2;

    for (int kt = 0; kt < nkt; kt++) {
        const float* Kg = Kb + (size_t)kt*64*HD;
        const float* Vg = Vb + (size_t)kt*64*HD;
        #pragma unroll
        for (int it = 0; it < 8; it++) {
            int slot = tid + it*256;
            int r = slot >> 5, c4 = (slot & 31) * 4;
            float4 kv = *(const float4*)(Kg + (size_t)r*HD + c4);
            *(float4*)(sK + (size_t)r*K_STRIDE + c4) = kv;
            float4 vv = *(const float4*)(Vg + (size_t)r*HD + c4);
            sV[(size_t)(c4+0)*V_STRIDE + r] = vv.x;
            sV[(size_t)(c4+1)*V_STRIDE + r] = vv.y;
            sV[(size_t)(c4+2)*V_STRIDE + r] = vv.z;
            sV[(size_t)(c4+3)*V_STRIDE + r] = vv.w;
        }
        __syncthreads();

        bool active = (kt*64 <= row_max);
        if (active) {
            /* ---- S = Q K^T (3xTF32) ---- */
            float s[8][4] = {};
            #pragma unroll
            for (int ks = 0; ks < 16; ks++) {
                const float* ab = sQ + (size_t)(m0 + gid)*Q_STRIDE + ks*8 + qd;
                uint32_t ahi[4], alo[4];
                split_tf32(ab[0],              ahi[0], alo[0]);
                split_tf32(ab[8*Q_STRIDE],     ahi[1], alo[1]);
                split_tf32(ab[4],              ahi[2], alo[2]);
                split_tf32(ab[8*Q_STRIDE + 4], ahi[3], alo[3]);
                #pragma unroll
                for (int nt = 0; nt < 8; nt++) {
                    const float* kb = sK + (size_t)(nt*8 + gid)*K_STRIDE + ks*8 + qd;
                    uint32_t bh0, bl0, bh1, bl1;
                    split_tf32(kb[0], bh0, bl0);
                    split_tf32(kb[4], bh1, bl1);
                    mma3(s[nt], ahi, alo, bh0, bh1, bl0, bl1);
                }
            }

            /* ---- causal mask (partial tiles only) ---- */
            if (kt*64 + 63 > row_min) {
                int rA = row_min + gid, rB = rA + 8;
                #pragma unroll
                for (int nt = 0; nt < 8; nt++) {
                    int c0 = kt*64 + nt*8 + 2*qd;
                    if (c0     > rA) s[nt][0] = -1e30f;
                    if (c0 + 1 > rA) s[nt][1] = -1e30f;
                    if (c0     > rB) s[nt][2] = -1e30f;
                    if (c0 + 1 > rB) s[nt][3] = -1e30f;
                }
            }

            /* ---- online softmax (rows A=gid, B=gid+8; 4-lane groups) ---- */
            float mA = -1e30f, mB = -1e30f;
            #pragma unroll
            for (int nt = 0; nt < 8; nt++) {
                mA = fmaxf(mA, fmaxf(s[nt][0], s[nt][1]));
                mB = fmaxf(mB, fmaxf(s[nt][2], s[nt][3]));
            }
            mA = fmaxf(mA, __shfl_xor_sync(0xffffffffu, mA, 1));
            mA = fmaxf(mA, __shfl_xor_sync(0xffffffffu, mA, 2));
            mB = fmaxf(mB, __shfl_xor_sync(0xffffffffu, mB, 1));
            mB = fmaxf(mB, __shfl_xor_sync(0xffffffffu, mB, 2));
            float newmA = fmaxf(miA, mA), newmB = fmaxf(miB, mB);
            float alA = __expf(miA - newmA), alB = __expf(miB - newmB);
            float sumA = 0.f, sumB = 0.f;
            #pragma unroll
            for (int nt = 0; nt < 8; nt++) {
                s[nt][0] = __expf(s[nt][0] - newmA);
                s[nt][1] = __expf(s[nt][1] - newmA);
                s[nt][2] = __expf(s[nt][2] - newmB);
                s[nt][3] = __expf(s[nt][3] - newmB);
                sumA += s[nt][0] + s[nt][1];
                sumB += s[nt][2] + s[nt][3];
            }
            sumA += __shfl_xor_sync(0xffffffffu, sumA, 1);
            sumA += __shfl_xor_sync(0xffffffffu, sumA, 2);
            sumB += __shfl_xor_sync(0xffffffffu, sumB, 1);
            sumB += __shfl_xor_sync(0xffffffffu, sumB, 2);
            liA = liA*alA + sumA;  miA = newmA;
            liB = liB*alB + sumB;  miB = newmB;

            /* ---- store P fp32 (own warp's rows only) ---- */
            {
                float* pA = sP + (size_t)(m0 + gid)    *P_STRIDE + 2*qd;
                float* pB = sP + (size_t)(m0 + gid + 8)*P_STRIDE + 2*qd;
                #pragma unroll
                for (int nt = 0; nt < 8; nt++) {
                    *(float2*)(pA + nt*8) = make_float2(s[nt][0], s[nt][1]);
                    *(float2*)(pB + nt*8) = make_float2(s[nt][2], s[nt][3]);
                }
            }
            __syncwarp();

            /* ---- rescale O ---- */
            #pragma unroll
            for (int nt = 0; nt < 16; nt++) {
                o[nt][0] *= alA; o[nt][1] *= alA;
                o[nt][2] *= alB; o[nt][3] *= alB;
            }

            /* ---- O += P V (3xTF32) ---- */
            #pragma unroll
            for (int ks = 0; ks < 8; ks++) {
                const float* pb = sP + (size_t)(m0 + gid)*P_STRIDE + ks*8 + qd;
                uint32_t phi[4], plo[4];
                split_tf32(pb[0],              phi[0], plo[0]);
                split_tf32(pb[8*P_STRIDE],     phi[1], plo[1]);
                split_tf32(pb[4],              phi[2], plo[2]);
                split_tf32(pb[8*P_STRIDE + 4], phi[3], plo[3]);
                #pragma unroll
                for (int nt = 0; nt < 16; nt++) {
                    const float* vb = sV + (size_t)(nt*8 + gid)*V_STRIDE + ks*8 + qd;
                    uint32_t bh0, bl0, bh1, bl1;
                    split_tf32(vb[0], bh0, bl0);
                    split_tf32(vb[4], bh1, bl1);
                    mma3(o[nt], phi, plo, bh0, bh1, bl0, bl1);
                }
            }
        }
        __syncthreads();
    }

    /* ---- epilogue: O/l -> g_ao [b, s, h*HD + d] ---- */
    float invA = 1.0f / liA, invB = 1.0f / liB;
    float* Og = g_ao + ((size_t)b*SEQ + (size_t)qt*128)*DIM + (size_t)h*HD;
    #pragma unroll
    for (int nt = 0; nt < 16; nt++) {
        int c = nt*8 + 2*qd;
        float2 vA = make_float2(o[nt][0]*invA, o[nt][1]*invA);
        float2 vB = make_float2(o[nt][2]*invB, o[nt][3]*invB);
        *(float2*)(Og + (size_t)(m0 + gid)    *DIM + c) = vA;
        *(float2*)(Og + (size_t)(m0 + gid + 8)*DIM + c) = vB;
    }
}

/* ========================= launch ========================= */
extern "C" void kernel_launch(void* const* d_in, const int* in_sizes, int n_in,
                              void* d_out, int out_size)
{
    const float* x  = (const float*)d_in[0];
    const float* wq = (const float*)d_in[1];
    const float* wk = (const float*)d_in[2];
    const float* wv = (const float*)d_in[3];
    const float* wo = (const float*)d_in[4];
    const float* Sq = (const float*)d_in[5];
    const float* Sk = (const float*)d_in[6];
    const float* Sv = (const float*)d_in[7];
    const float* So = (const float*)d_in[8];
    const float* fr = (const float*)d_in[9];
    float* out = (float*)d_out;

    cudaFuncSetAttribute(k_flash, cudaFuncAttributeMaxDynamicSharedMemorySize,
                         FLASH_SMEM);

    dim3 blk(256);
    /* AS_{q,k,v} = x @ S / 64 */
    k_gemm<<<dim3(32, 3, BATCH), blk>>>(x, Sq, Sk, Sv, So, wq, wk, wv, wo, 0);
    /* T_{q,k,v,o} = w @ S */
    k_gemm<<<dim3(32, 4, BATCH), blk>>>(x, Sq, Sk, Sv, So, wq, wk, wv, wo, 1);
    /* q/k/v projections (+RoPE, layout to [b,h,s,d]) */
    k_proj<<<dim3(32, 32, BATCH), blk>>>(fr, out, 0);
    k_proj<<<dim3(32, 16, BATCH), blk>>>(fr, out, 1);
    k_proj<<<dim3(32, 16, BATCH), blk>>>(fr, out, 2);
    /* causal flash attention (3xTF32 tensor cores) -> g_ao [b,s,DIM] */
    k_flash<<<dim3(SEQ/128, NH, BATCH), blk, FLASH_SMEM>>>();
    /* AS_o = attn_out @ So / 64 */
    k_gemm<<<dim3(32, 1, BATCH), blk>>>(x, Sq, Sk, Sv, So, wq, wk, wv, wo, 2);
    /* final = AS_o @ To^T -> d_out */
    k_proj<<<dim3(32, 32, BATCH), blk>>>(fr, out, 3);
}

// round 4
// speedup vs baseline: 1.2744x; 1.0345x over previous
#include <cuda_runtime.h>
#include <math.h>
#include <stdint.h>

#define BATCH 2
#define SEQ   2048
#define DIM   2048
#define NH    16
#define NKV   8
#define HD    128
#define KVD   (NKV*HD)
#define SK    64
#define INV_SQRT_HD 0.08838834764831845f  /* 1/sqrt(128) */

/* ------------------------- scratch (static device) ------------------------ */
__device__ float g_ASq[(size_t)BATCH*SEQ*SK];
__device__ float g_ASk[(size_t)BATCH*SEQ*SK];
__device__ float g_ASv[(size_t)BATCH*SEQ*SK];
__device__ float g_ASo[(size_t)BATCH*SEQ*SK];
__device__ float g_Tq [(size_t)BATCH*DIM*SK];
__device__ float g_Tk [(size_t)BATCH*KVD*SK];
__device__ float g_Tv [(size_t)BATCH*KVD*SK];
__device__ float g_To [(size_t)BATCH*DIM*SK];
__device__ float g_q  [(size_t)BATCH*NH *SEQ*HD];
__device__ float g_k  [(size_t)BATCH*NKV*SEQ*HD];
__device__ float g_v  [(size_t)BATCH*NKV*SEQ*HD];
__device__ float g_ao [(size_t)BATCH*SEQ*DIM];

/* ---------------------- tf32 / mma helpers ---------------------- */
__device__ __forceinline__ uint32_t f2tf32(float f) {
    uint32_t u;
    asm("cvt.rna.tf32.f32 %0, %1;" : "=r"(u) : "f"(f));
    return u;
}
__device__ __forceinline__ float f2tf32f(float f) {
    return __uint_as_float(f2tf32(f));
}
/* 3xTF32 split: f = hi + lo with ~21 effective mantissa bits */
__device__ __forceinline__ void split_tf32(float f, uint32_t& hi, uint32_t& lo) {
    float h = f2tf32f(f);
    hi = __float_as_uint(h);
    lo = f2tf32(f - h);
}
__device__ __forceinline__ void split_tf32f(float f, float& hi, float& lo) {
    float h = f2tf32f(f);
    hi = h;
    lo = __uint_as_float(f2tf32(f - h));
}
__device__ __forceinline__ void mma_tf32(float* c, const uint32_t* a,
                                         uint32_t b0, uint32_t b1) {
    asm volatile(
        "mma.sync.aligned.m16n8k8.row.col.f32.tf32.tf32.f32 "
        "{%0,%1,%2,%3}, {%4,%5,%6,%7}, {%8,%9}, {%0,%1,%2,%3};"
        : "+f"(c[0]), "+f"(c[1]), "+f"(c[2]), "+f"(c[3])
        : "r"(a[0]), "r"(a[1]), "r"(a[2]), "r"(a[3]), "r"(b0), "r"(b1));
}
__device__ __forceinline__ void mma3(float* c,
                                     const uint32_t* ahi, const uint32_t* alo,
                                     uint32_t bh0, uint32_t bh1,
                                     uint32_t bl0, uint32_t bl1) {
    mma_tf32(c, alo, bh0, bh1);   /* small terms first */
    mma_tf32(c, ahi, bl0, bl1);
    mma_tf32(c, ahi, bh0, bh1);
}

/* =====================================================================
 * k_gemm: 64x64 tile of C = alpha * A(MxK,row) * B(Kx64,row)  (fp32)
 * =====================================================================*/
__global__ __launch_bounds__(256) void k_gemm(
    const float* __restrict__ x,
    const float* __restrict__ Sq, const float* __restrict__ Sk,
    const float* __restrict__ Sv, const float* __restrict__ So,
    const float* __restrict__ wq, const float* __restrict__ wk,
    const float* __restrict__ wv, const float* __restrict__ wo,
    int mode)
{
    int b = blockIdx.z, which = blockIdx.y;
    int m0 = blockIdx.x * 64;
    const float* A; const float* Bm; float* C; float alpha;
    const int K = DIM;

    if (mode == 0) {
        A  = x + (size_t)b*SEQ*DIM;
        Bm = (which==0 ? Sq : which==1 ? Sk : Sv) + (size_t)b*DIM*SK;
        C  = (which==0 ? g_ASq : which==1 ? g_ASk : g_ASv) + (size_t)b*SEQ*SK;
        alpha = 1.0f/SK;
    } else if (mode == 1) {
        int M = (which==0 || which==3) ? DIM : KVD;
        if (m0 >= M) return;
        A  = (which==0 ? wq : which==1 ? wk : which==2 ? wv : wo);
        Bm = (which==0 ? Sq : which==1 ? Sk : which==2 ? Sv : So) + (size_t)b*DIM*SK;
        C  = (which==0 ? g_Tq + (size_t)b*DIM*SK :
              which==1 ? g_Tk + (size_t)b*KVD*SK :
              which==2 ? g_Tv + (size_t)b*KVD*SK :
                         g_To + (size_t)b*DIM*SK);
        alpha = 1.0f;
    } else {
        A  = g_ao + (size_t)b*SEQ*DIM;
        Bm = So   + (size_t)b*DIM*SK;
        C  = g_ASo + (size_t)b*SEQ*SK;
        alpha = 1.0f/SK;
    }
    A += (size_t)m0 * K;

    __shared__ float sA[16][68];
    __shared__ float sB[16][64];

    int tid = threadIdx.x;
    int tx = tid & 15, ty = tid >> 4;
    int la_r = tid >> 2,  la_c = (tid & 3)  * 4;
    int lb_r = tid >> 4,  lb_c = (tid & 15) * 4;

    float acc[4][4] = {};

    for (int k0 = 0; k0 < K; k0 += 16) {
        float4 av = *(const float4*)(A  + (size_t)la_r * K + k0 + la_c);
        float4 bv = *(const float4*)(Bm + (size_t)(k0 + lb_r) * SK + lb_c);
        __syncthreads();
        sA[la_c+0][la_r] = av.x; sA[la_c+1][la_r] = av.y;
        sA[la_c+2][la_r] = av.z; sA[la_c+3][la_r] = av.w;
        *(float4*)&sB[lb_r][lb_c] = bv;
        __syncthreads();
        #pragma unroll
        for (int kk = 0; kk < 16; kk++) {
            float4 a  = *(const float4*)&sA[kk][ty*4];
            float4 bb = *(const float4*)&sB[kk][tx*4];
            acc[0][0]+=a.x*bb.x; acc[0][1]+=a.x*bb.y; acc[0][2]+=a.x*bb.z; acc[0][3]+=a.x*bb.w;
            acc[1][0]+=a.y*bb.x; acc[1][1]+=a.y*bb.y; acc[1][2]+=a.y*bb.z; acc[1][3]+=a.y*bb.w;
            acc[2][0]+=a.z*bb.x; acc[2][1]+=a.z*bb.y; acc[2][2]+=a.z*bb.z; acc[2][3]+=a.z*bb.w;
            acc[3][0]+=a.w*bb.x; acc[3][1]+=a.w*bb.y; acc[3][2]+=a.w*bb.z; acc[3][3]+=a.w*bb.w;
        }
    }
    #pragma unroll
    for (int i = 0; i < 4; i++) {
        float4 o = make_float4(acc[i][0]*alpha, acc[i][1]*alpha,
                               acc[i][2]*alpha, acc[i][3]*alpha);
        *(float4*)(C + (size_t)(m0 + ty*4 + i) * SK + tx*4) = o;
    }
}

/* =====================================================================
 * k_proj: 64x64 tile of  X = AS (Sx64) @ T^T (64xM)   (K = 64, fp32)
 * =====================================================================*/
__global__ __launch_bounds__(256) void k_proj(const float* __restrict__ freqs,
                                              float* __restrict__ dout, int mode)
{
    int b  = blockIdx.z;
    int s0 = blockIdx.x * 64, m0 = blockIdx.y * 64;

    const float* ASp; const float* Tp;
    if      (mode == 0) { ASp = g_ASq + (size_t)b*SEQ*SK; Tp = g_Tq + (size_t)b*DIM*SK; }
    else if (mode == 1) { ASp = g_ASk + (size_t)b*SEQ*SK; Tp = g_Tk + (size_t)b*KVD*SK; }
    else if (mode == 2) { ASp = g_ASv + (size_t)b*SEQ*SK; Tp = g_Tv + (size_t)b*KVD*SK; }
    else                { ASp = g_ASo + (size_t)b*SEQ*SK; Tp = g_To + (size_t)b*DIM*SK; }

    __shared__ float sA[64][68];
    __shared__ float sB[64][68];

    int tid = threadIdx.x, tx = tid & 15, ty = tid >> 4;

    #pragma unroll
    for (int it = 0; it < 4; it++) {
        int r  = (tid >> 4) + it*16;
        int c4 = (tid & 15) * 4;
        float4 a = *(const float4*)(ASp + (size_t)(s0 + r)*SK + c4);
        sA[c4+0][r]=a.x; sA[c4+1][r]=a.y; sA[c4+2][r]=a.z; sA[c4+3][r]=a.w;
        float4 t = *(const float4*)(Tp  + (size_t)(m0 + r)*SK + c4);
        sB[c4+0][r]=t.x; sB[c4+1][r]=t.y; sB[c4+2][r]=t.z; sB[c4+3][r]=t.w;
    }
    __syncthreads();

    float acc[4][4] = {};
    #pragma unroll
    for (int k = 0; k < 64; k++) {
        float4 a  = *(const float4*)&sA[k][ty*4];
        float4 bb = *(const float4*)&sB[k][tx*4];
        acc[0][0]+=a.x*bb.x; acc[0][1]+=a.x*bb.y; acc[0][2]+=a.x*bb.z; acc[0][3]+=a.x*bb.w;
        acc[1][0]+=a.y*bb.x; acc[1][1]+=a.y*bb.y; acc[1][2]+=a.y*bb.z; acc[1][3]+=a.y*bb.w;
        acc[2][0]+=a.z*bb.x; acc[2][1]+=a.z*bb.y; acc[2][2]+=a.z*bb.z; acc[2][3]+=a.z*bb.w;
        acc[3][0]+=a.w*bb.x; acc[3][1]+=a.w*bb.y; acc[3][2]+=a.w*bb.z; acc[3][3]+=a.w*bb.w;
    }

    if (mode == 3) {
        #pragma unroll
        for (int i = 0; i < 4; i++) {
            *(float4*)(dout + ((size_t)b*SEQ + s0 + ty*4 + i)*DIM + m0 + tx*4) =
                make_float4(acc[i][0], acc[i][1], acc[i][2], acc[i][3]);
        }
    } else if (mode == 2) {
        int h  = m0 >> 7;
        int d0 = (m0 & 127) + tx*4;
        float* base = g_v + ((size_t)(b*NKV + h))*SEQ*HD;
        #pragma unroll
        for (int i = 0; i < 4; i++) {
            *(float4*)(base + (size_t)(s0 + ty*4 + i)*HD + d0) =
                make_float4(acc[i][0], acc[i][1], acc[i][2], acc[i][3]);
        }
    } else {
        int h  = m0 >> 7;
        int d0 = (m0 & 127) + tx*4;
        int dh = d0 >> 1;
        float* base = (mode == 0) ? g_q + ((size_t)(b*NH  + h))*SEQ*HD
                                  : g_k + ((size_t)(b*NKV + h))*SEQ*HD;
        #pragma unroll
        for (int i = 0; i < 4; i++) {
            int srow = s0 + ty*4 + i;
            const float* f = freqs + ((size_t)srow*64 + dh)*2;
            float c0 = f[0], n0 = f[1], c1 = f[2], n1 = f[3];
            float e0 = acc[i][0]*n0 - acc[i][1]*c0;
            float o0 = acc[i][0]*c0 + acc[i][1]*n0;
            float e1 = acc[i][2]*n1 - acc[i][3]*c1;
            float o1 = acc[i][2]*c1 + acc[i][3]*n1;
            *(float4*)(base + (size_t)srow*HD + d0) = make_float4(e0, o0, e1, o1);
        }
    }
}

/* =====================================================================
 * k_flash: causal flash attention via 3xTF32 mma.sync (fp32-accurate).
 *   BM=128, BN=64, 8 warps, warp-local softmax (16 rows/warp).
 *   K and V are split hi/lo COOPERATIVELY into smem once per tile;
 *   Q and P split in registers once per k-step. Inner loop = LDS + MMA.
 *   P aliases the K smem region (K dead after QK; guarded by sync).
 *   grid (SEQ/128, NH, B); GQA kv head = h>>1; tail-first scheduling.
 * =====================================================================*/
#define Q_STRIDE  132
#define K_STRIDE  132
#define V_STRIDE  68
#define P_STRIDE  68
#define SQ_OFF    0
#define SKHI_OFF  (128*Q_STRIDE)
#define SKLO_OFF  (SKHI_OFF + 64*K_STRIDE)
#define SP_OFF    SKHI_OFF                       /* P aliases K hi/lo */
#define SVHI_OFF  (SKLO_OFF + 64*K_STRIDE)
#define SVLO_OFF  (SVHI_OFF + 128*V_STRIDE)
#define FLASH_SMEM ((SVLO_OFF + 128*V_STRIDE) * 4)   /* 204800 B */

__global__ void __launch_bounds__(256, 1) k_flash()
{
    extern __shared__ float sm[];
    float* sQ   = sm + SQ_OFF;    /* [m][d] fp32 raw (scaled) */
    float* sKhi = sm + SKHI_OFF;  /* [n][d] tf32 hi */
    float* sKlo = sm + SKLO_OFF;  /* [n][d] tf32 lo */
    float* sVhi = sm + SVHI_OFF;  /* [d][p] tf32 hi (transposed) */
    float* sVlo = sm + SVLO_OFF;  /* [d][p] tf32 lo (transposed) */
    float* sP   = sm + SP_OFF;    /* [m][p] fp32 raw (aliases K) */

    int tid = threadIdx.x, lane = tid & 31, w = tid >> 5;
    int qt = (int)gridDim.x - 1 - (int)blockIdx.x;     /* heavy tiles first */
    int h = blockIdx.y, b = blockIdx.z;
    int gid = lane >> 2, qd = lane & 3;

    const float* Qg = g_q + ((size_t)(b*NH  + h))     *SEQ*HD + (size_t)qt*128*HD;
    const float* Kb = g_k + ((size_t)(b*NKV + (h>>1)))*SEQ*HD;
    const float* Vb = g_v + ((size_t)(b*NKV + (h>>1)))*SEQ*HD;

    /* ---- load Q tile (scaled fp32) ---- */
    #pragma unroll
    for (int it = 0; it < 16; it++) {
        int slot = tid + it*256;
        int r = slot >> 5, c4 = (slot & 31) * 4;
        float4 v = *(const float4*)(Qg + (size_t)r*HD + c4);
        float* d = sQ + (size_t)r*Q_STRIDE + c4;
        d[0] = v.x*INV_SQRT_HD; d[1] = v.y*INV_SQRT_HD;
        d[2] = v.z*INV_SQRT_HD; d[3] = v.w*INV_SQRT_HD;
    }

    int m0 = w*16;
    float o[16][4] = {};
    float miA = -1e30f, miB = -1e30f, liA = 0.f, liB = 0.f;
    int row_min = qt*128 + w*16;
    int row_max = row_min + 15;
    int nkt = 2*qt + 2;

    for (int kt = 0; kt < nkt; kt++) {
        const float* Kg = Kb + (size_t)kt*64*HD;
        const float* Vg = Vb + (size_t)kt*64*HD;
        /* ---- cooperative load + hi/lo split of K and V ---- */
        #pragma unroll
        for (int it = 0; it < 8; it++) {
            int slot = tid + it*256;
            int r = slot >> 5, c4 = (slot & 31) * 4;
            float4 kv = *(const float4*)(Kg + (size_t)r*HD + c4);
            float4 khi, klo;
            split_tf32f(kv.x, khi.x, klo.x);
            split_tf32f(kv.y, khi.y, klo.y);
            split_tf32f(kv.z, khi.z, klo.z);
            split_tf32f(kv.w, khi.w, klo.w);
            *(float4*)(sKhi + (size_t)r*K_STRIDE + c4) = khi;
            *(float4*)(sKlo + (size_t)r*K_STRIDE + c4) = klo;
            float4 vv = *(const float4*)(Vg + (size_t)r*HD + c4);
            float vh, vl;
            split_tf32f(vv.x, vh, vl);
            sVhi[(size_t)(c4+0)*V_STRIDE + r] = vh;
            sVlo[(size_t)(c4+0)*V_STRIDE + r] = vl;
            split_tf32f(vv.y, vh, vl);
            sVhi[(size_t)(c4+1)*V_STRIDE + r] = vh;
            sVlo[(size_t)(c4+1)*V_STRIDE + r] = vl;
            split_tf32f(vv.z, vh, vl);
            sVhi[(size_t)(c4+2)*V_STRIDE + r] = vh;
            sVlo[(size_t)(c4+2)*V_STRIDE + r] = vl;
            split_tf32f(vv.w, vh, vl);
            sVhi[(size_t)(c4+3)*V_STRIDE + r] = vh;
            sVlo[(size_t)(c4+3)*V_STRIDE + r] = vl;
        }
        __syncthreads();

        bool active = (kt*64 <= row_max);
        float s[8][4] = {};
        if (active) {
            /* ---- S = Q K^T (3xTF32; Q split in regs per ks) ---- */
            #pragma unroll
            for (int ks = 0; ks < 16; ks++) {
                const float* ab = sQ + (size_t)(m0 + gid)*Q_STRIDE + ks*8 + qd;
                uint32_t ahi[4], alo[4];
                split_tf32(ab[0],              ahi[0], alo[0]);
                split_tf32(ab[8*Q_STRIDE],     ahi[1], alo[1]);
                split_tf32(ab[4],              ahi[2], alo[2]);
                split_tf32(ab[8*Q_STRIDE + 4], ahi[3], alo[3]);
                #pragma unroll
                for (int nt = 0; nt < 8; nt++) {
                    size_t koff = (size_t)(nt*8 + gid)*K_STRIDE + ks*8 + qd;
                    uint32_t bh0 = __float_as_uint(sKhi[koff]);
                    uint32_t bh1 = __float_as_uint(sKhi[koff + 4]);
                    uint32_t bl0 = __float_as_uint(sKlo[koff]);
                    uint32_t bl1 = __float_as_uint(sKlo[koff + 4]);
                    mma3(s[nt], ahi, alo, bh0, bh1, bl0, bl1);
                }
            }

            /* ---- causal mask (partial tiles only) ---- */
            if (kt*64 + 63 > row_min) {
                int rA = row_min + gid, rB = rA + 8;
                #pragma unroll
                for (int nt = 0; nt < 8; nt++) {
                    int c0 = kt*64 + nt*8 + 2*qd;
                    if (c0     > rA) s[nt][0] = -1e30f;
                    if (c0 + 1 > rA) s[nt][1] = -1e30f;
                    if (c0     > rB) s[nt][2] = -1e30f;
                    if (c0 + 1 > rB) s[nt][3] = -1e30f;
                }
            }

            /* ---- online softmax (register-only; rows A=gid, B=gid+8) ---- */
            float mA = -1e30f, mB = -1e30f;
            #pragma unroll
            for (int nt = 0; nt < 8; nt++) {
                mA = fmaxf(mA, fmaxf(s[nt][0], s[nt][1]));
                mB = fmaxf(mB, fmaxf(s[nt][2], s[nt][3]));
            }
            mA = fmaxf(mA, __shfl_xor_sync(0xffffffffu, mA, 1));
            mA = fmaxf(mA, __shfl_xor_sync(0xffffffffu, mA, 2));
            mB = fmaxf(mB, __shfl_xor_sync(0xffffffffu, mB, 1));
            mB = fmaxf(mB, __shfl_xor_sync(0xffffffffu, mB, 2));
            float newmA = fmaxf(miA, mA), newmB = fmaxf(miB, mB);
            float alA = __expf(miA - newmA), alB = __expf(miB - newmB);
            float sumA = 0.f, sumB = 0.f;
            #pragma unroll
            for (int nt = 0; nt < 8; nt++) {
                s[nt][0] = __expf(s[nt][0] - newmA);
                s[nt][1] = __expf(s[nt][1] - newmA);
                s[nt][2] = __expf(s[nt][2] - newmB);
                s[nt][3] = __expf(s[nt][3] - newmB);
                sumA += s[nt][0] + s[nt][1];
                sumB += s[nt][2] + s[nt][3];
            }
            sumA += __shfl_xor_sync(0xffffffffu, sumA, 1);
            sumA += __shfl_xor_sync(0xffffffffu, sumA, 2);
            sumB += __shfl_xor_sync(0xffffffffu, sumB, 1);
            sumB += __shfl_xor_sync(0xffffffffu, sumB, 2);
            liA = liA*alA + sumA;  miA = newmA;
            liB = liB*alB + sumB;  miB = newmB;

            /* ---- rescale O (register-only) ---- */
            #pragma unroll
            for (int nt = 0; nt < 16; nt++) {
                o[nt][0] *= alA; o[nt][1] *= alA;
                o[nt][2] *= alB; o[nt][3] *= alB;
            }
        }
        /* K-region reads complete before P (aliased) is written */
        __syncthreads();

        if (active) {
            /* ---- store P fp32 (own warp's rows only) ---- */
            float* pA = sP + (size_t)(m0 + gid)    *P_STRIDE + 2*qd;
            float* pB = sP + (size_t)(m0 + gid + 8)*P_STRIDE + 2*qd;
            #pragma unroll
            for (int nt = 0; nt < 8; nt++) {
                *(float2*)(pA + nt*8) = make_float2(s[nt][0], s[nt][1]);
                *(float2*)(pB + nt*8) = make_float2(s[nt][2], s[nt][3]);
            }
            __syncwarp();

            /* ---- O += P V (3xTF32; P split in regs per ks) ---- */
            #pragma unroll
            for (int ks = 0; ks < 8; ks++) {
                const float* pb = sP + (size_t)(m0 + gid)*P_STRIDE + ks*8 + qd;
                uint32_t phi[4], plo[4];
                split_tf32(pb[0],              phi[0], plo[0]);
                split_tf32(pb[8*P_STRIDE],     phi[1], plo[1]);
                split_tf32(pb[4],              phi[2], plo[2]);
                split_tf32(pb[8*P_STRIDE + 4], phi[3], plo[3]);
                #pragma unroll
                for (int nt = 0; nt < 16; nt++) {
                    size_t voff = (size_t)(nt*8 + gid)*V_STRIDE + ks*8 + qd;
                    uint32_t bh0 = __float_as_uint(sVhi[voff]);
                    uint32_t bh1 = __float_as_uint(sVhi[voff + 4]);
                    uint32_t bl0 = __float_as_uint(sVlo[voff]);
                    uint32_t bl1 = __float_as_uint(sVlo[voff + 4]);
                    mma3(o[nt], phi, plo, bh0, bh1, bl0, bl1);
                }
            }
        }
        __syncthreads();
    }

    /* ---- epilogue: O/l -> g_ao [b, s, h*HD + d] ---- */
    float invA = 1.0f / liA, invB = 1.0f / liB;
    float* Og = g_ao + ((size_t)b*SEQ + (size_t)qt*128)*DIM + (size_t)h*HD;
    #pragma unroll
    for (int nt = 0; nt < 16; nt++) {
        int c = nt*8 + 2*qd;
        float2 vA = make_float2(o[nt][0]*invA, o[nt][1]*invA);
        float2 vB = make_float2(o[nt][2]*invB, o[nt][3]*invB);
        *(float2*)(Og + (size_t)(m0 + gid)    *DIM + c) = vA;
        *(float2*)(Og + (size_t)(m0 + gid + 8)*DIM + c) = vB;
    }
}

/* ========================= launch ========================= */
extern "C" void kernel_launch(void* const* d_in, const int* in_sizes, int n_in,
                              void* d_out, int out_size)
{
    const float* x  = (const float*)d_in[0];
    const float* wq = (const float*)d_in[1];
    const float* wk = (const float*)d_in[2];
    const float* wv = (const float*)d_in[3];
    const float* wo = (const float*)d_in[4];
    const float* Sq = (const float*)d_in[5];
    const float* Sk = (const float*)d_in[6];
    const float* Sv = (const float*)d_in[7];
    const float* So = (const float*)d_in[8];
    const float* fr = (const float*)d_in[9];
    float* out = (float*)d_out;

    cudaFuncSetAttribute(k_flash, cudaFuncAttributeMaxDynamicSharedMemorySize,
                         FLASH_SMEM);

    dim3 blk(256);
    /* AS_{q,k,v} = x @ S / 64 */
    k_gemm<<<dim3(32, 3, BATCH), blk>>>(x, Sq, Sk, Sv, So, wq, wk, wv, wo, 0);
    /* T_{q,k,v,o} = w @ S */
    k_gemm<<<dim3(32, 4, BATCH), blk>>>(x, Sq, Sk, Sv, So, wq, wk, wv, wo, 1);
    /* q/k/v projections (+RoPE, layout to [b,h,s,d]) */
    k_proj<<<dim3(32, 32, BATCH), blk>>>(fr, out, 0);
    k_proj<<<dim3(32, 16, BATCH), blk>>>(fr, out, 1);
    k_proj<<<dim3(32, 16, BATCH), blk>>>(fr, out, 2);
    /* causal flash attention (3xTF32, smem-split K/V) -> g_ao */
    k_flash<<<dim3(SEQ/128, NH, BATCH), blk, FLASH_SMEM>>>();
    /* AS_o = attn_out @ So / 64 */
    k_gemm<<<dim3(32, 1, BATCH), blk>>>(x, Sq, Sk, Sv, So, wq, wk, wv, wo, 2);
    /* final = AS_o @ To^T -> d_out */
    k_proj<<<dim3(32, 32, BATCH), blk>>>(fr, out, 3);
}

// round 10
// speedup vs baseline: 1.7965x; 1.4097x over previous
#include <cuda_runtime.h>
#include <cuda_bf16.h>
#include <math.h>
#include <stdint.h>

#define BATCH 2
#define SEQ   2048
#define DIM   2048
#define NH    16
#define NKV   8
#define HD    128
#define KVD   (NKV*HD)
#define SK    64
#define INV_SQRT_HD 0.08838834764831845f  /* 1/sqrt(128) */

/* ------------------------- scratch (static device) ------------------------ */
__device__ float g_ASq[(size_t)BATCH*SEQ*SK];
__device__ float g_ASk[(size_t)BATCH*SEQ*SK];
__device__ float g_ASv[(size_t)BATCH*SEQ*SK];
__device__ float g_ASo[(size_t)BATCH*SEQ*SK];
__device__ float g_Tq [(size_t)BATCH*DIM*SK];
__device__ float g_Tk [(size_t)BATCH*KVD*SK];
__device__ float g_Tv [(size_t)BATCH*KVD*SK];
__device__ float g_To [(size_t)BATCH*DIM*SK];
__device__ float g_q  [(size_t)BATCH*NH *SEQ*HD];
__device__ float g_k  [(size_t)BATCH*NKV*SEQ*HD];
__device__ float g_v  [(size_t)BATCH*NKV*SEQ*HD];
__device__ float g_ao [(size_t)BATCH*SEQ*DIM];

/* ---------------------- bf16 split / mma helpers ---------------------- */
__device__ __forceinline__ uint32_t pack_bf16(float a, float b) {
    __nv_bfloat162 t = __floats2bfloat162_rn(a, b);
    return *reinterpret_cast<uint32_t*>(&t);
}
/* 2-term bf16 split of a pair: (hi word, lo word), ~16-17 mantissa bits */
__device__ __forceinline__ void split2(float a, float b,
                                       uint32_t& hi, uint32_t& lo) {
    float ha = __bfloat162float(__float2bfloat16_rn(a));
    float hb = __bfloat162float(__float2bfloat16_rn(b));
    hi = pack_bf16(ha, hb);
    lo = pack_bf16(a - ha, b - hb);
}
__device__ __forceinline__ void mma_bf16(float* c, const uint32_t* a,
                                         uint32_t b0, uint32_t b1) {
    asm volatile(
        "mma.sync.aligned.m16n8k16.row.col.f32.bf16.bf16.f32 "
        "{%0,%1,%2,%3}, {%4,%5,%6,%7}, {%8,%9}, {%0,%1,%2,%3};"
        : "+f"(c[0]), "+f"(c[1]), "+f"(c[2]), "+f"(c[3])
        : "r"(a[0]), "r"(a[1]), "r"(a[2]), "r"(a[3]), "r"(b0), "r"(b1));
}
/* c += (ah+al)*(bh+bl) dropping al*bl; small terms first */
__device__ __forceinline__ void mma3b(float* c,
                                      const uint32_t* ah, const uint32_t* al,
                                      uint32_t bh0, uint32_t bh1,
                                      uint32_t bl0, uint32_t bl1) {
    mma_bf16(c, al, bh0, bh1);
    mma_bf16(c, ah, bl0, bl1);
    mma_bf16(c, ah, bh0, bh1);
}

/* =====================================================================
 * k_gemm: 64x64 tile of C = alpha * A(MxK,row) * B(Kx64,row)  (fp32)
 * =====================================================================*/
__global__ __launch_bounds__(256) void k_gemm(
    const float* __restrict__ x,
    const float* __restrict__ Sq, const float* __restrict__ Sk,
    const float* __restrict__ Sv, const float* __restrict__ So,
    const float* __restrict__ wq, const float* __restrict__ wk,
    const float* __restrict__ wv, const float* __restrict__ wo,
    int mode)
{
    int b = blockIdx.z, which = blockIdx.y;
    int m0 = blockIdx.x * 64;
    const float* A; const float* Bm; float* C; float alpha;
    const int K = DIM;

    if (mode == 0) {
        A  = x + (size_t)b*SEQ*DIM;
        Bm = (which==0 ? Sq : which==1 ? Sk : Sv) + (size_t)b*DIM*SK;
        C  = (which==0 ? g_ASq : which==1 ? g_ASk : g_ASv) + (size_t)b*SEQ*SK;
        alpha = 1.0f/SK;
    } else if (mode == 1) {
        int M = (which==0 || which==3) ? DIM : KVD;
        if (m0 >= M) return;
        A  = (which==0 ? wq : which==1 ? wk : which==2 ? wv : wo);
        Bm = (which==0 ? Sq : which==1 ? Sk : which==2 ? Sv : So) + (size_t)b*DIM*SK;
        C  = (which==0 ? g_Tq + (size_t)b*DIM*SK :
              which==1 ? g_Tk + (size_t)b*KVD*SK :
              which==2 ? g_Tv + (size_t)b*KVD*SK :
                         g_To + (size_t)b*DIM*SK);
        alpha = 1.0f;
    } else {
        A  = g_ao + (size_t)b*SEQ*DIM;
        Bm = So   + (size_t)b*DIM*SK;
        C  = g_ASo + (size_t)b*SEQ*SK;
        alpha = 1.0f/SK;
    }
    A += (size_t)m0 * K;

    __shared__ float sA[16][68];
    __shared__ float sB[16][64];

    int tid = threadIdx.x;
    int tx = tid & 15, ty = tid >> 4;
    int la_r = tid >> 2,  la_c = (tid & 3)  * 4;
    int lb_r = tid >> 4,  lb_c = (tid & 15) * 4;

    float acc[4][4] = {};

    for (int k0 = 0; k0 < K; k0 += 16) {
        float4 av = *(const float4*)(A  + (size_t)la_r * K + k0 + la_c);
        float4 bv = *(const float4*)(Bm + (size_t)(k0 + lb_r) * SK + lb_c);
        __syncthreads();
        sA[la_c+0][la_r] = av.x; sA[la_c+1][la_r] = av.y;
        sA[la_c+2][la_r] = av.z; sA[la_c+3][la_r] = av.w;
        *(float4*)&sB[lb_r][lb_c] = bv;
        __syncthreads();
        #pragma unroll
        for (int kk = 0; kk < 16; kk++) {
            float4 a  = *(const float4*)&sA[kk][ty*4];
            float4 bb = *(const float4*)&sB[kk][tx*4];
            acc[0][0]+=a.x*bb.x; acc[0][1]+=a.x*bb.y; acc[0][2]+=a.x*bb.z; acc[0][3]+=a.x*bb.w;
            acc[1][0]+=a.y*bb.x; acc[1][1]+=a.y*bb.y; acc[1][2]+=a.y*bb.z; acc[1][3]+=a.y*bb.w;
            acc[2][0]+=a.z*bb.x; acc[2][1]+=a.z*bb.y; acc[2][2]+=a.z*bb.z; acc[2][3]+=a.z*bb.w;
            acc[3][0]+=a.w*bb.x; acc[3][1]+=a.w*bb.y; acc[3][2]+=a.w*bb.z; acc[3][3]+=a.w*bb.w;
        }
    }
    #pragma unroll
    for (int i = 0; i < 4; i++) {
        float4 o = make_float4(acc[i][0]*alpha, acc[i][1]*alpha,
                               acc[i][2]*alpha, acc[i][3]*alpha);
        *(float4*)(C + (size_t)(m0 + ty*4 + i) * SK + tx*4) = o;
    }
}

/* =====================================================================
 * k_proj: 64x64 tile of  X = AS (Sx64) @ T^T (64xM)   (K = 64, fp32)
 * =====================================================================*/
__global__ __launch_bounds__(256) void k_proj(const float* __restrict__ freqs,
                                              float* __restrict__ dout, int mode)
{
    int b  = blockIdx.z;
    int s0 = blockIdx.x * 64, m0 = blockIdx.y * 64;

    const float* ASp; const float* Tp;
    if      (mode == 0) { ASp = g_ASq + (size_t)b*SEQ*SK; Tp = g_Tq + (size_t)b*DIM*SK; }
    else if (mode == 1) { ASp = g_ASk + (size_t)b*SEQ*SK; Tp = g_Tk + (size_t)b*KVD*SK; }
    else if (mode == 2) { ASp = g_ASv + (size_t)b*SEQ*SK; Tp = g_Tv + (size_t)b*KVD*SK; }
    else                { ASp = g_ASo + (size_t)b*SEQ*SK; Tp = g_To + (size_t)b*DIM*SK; }

    __shared__ float sA[64][68];
    __shared__ float sB[64][68];

    int tid = threadIdx.x, tx = tid & 15, ty = tid >> 4;

    #pragma unroll
    for (int it = 0; it < 4; it++) {
        int r  = (tid >> 4) + it*16;
        int c4 = (tid & 15) * 4;
        float4 a = *(const float4*)(ASp + (size_t)(s0 + r)*SK + c4);
        sA[c4+0][r]=a.x; sA[c4+1][r]=a.y; sA[c4+2][r]=a.z; sA[c4+3][r]=a.w;
        float4 t = *(const float4*)(Tp  + (size_t)(m0 + r)*SK + c4);
        sB[c4+0][r]=t.x; sB[c4+1][r]=t.y; sB[c4+2][r]=t.z; sB[c4+3][r]=t.w;
    }
    __syncthreads();

    float acc[4][4] = {};
    #pragma unroll
    for (int k = 0; k < 64; k++) {
        float4 a  = *(const float4*)&sA[k][ty*4];
        float4 bb = *(const float4*)&sB[k][tx*4];
        acc[0][0]+=a.x*bb.x; acc[0][1]+=a.x*bb.y; acc[0][2]+=a.x*bb.z; acc[0][3]+=a.x*bb.w;
        acc[1][0]+=a.y*bb.x; acc[1][1]+=a.y*bb.y; acc[1][2]+=a.y*bb.z; acc[1][3]+=a.y*bb.w;
        acc[2][0]+=a.z*bb.x; acc[2][1]+=a.z*bb.y; acc[2][2]+=a.z*bb.z; acc[2][3]+=a.z*bb.w;
        acc[3][0]+=a.w*bb.x; acc[3][1]+=a.w*bb.y; acc[3][2]+=a.w*bb.z; acc[3][3]+=a.w*bb.w;
    }

    if (mode == 3) {
        #pragma unroll
        for (int i = 0; i < 4; i++) {
            *(float4*)(dout + ((size_t)b*SEQ + s0 + ty*4 + i)*DIM + m0 + tx*4) =
                make_float4(acc[i][0], acc[i][1], acc[i][2], acc[i][3]);
        }
    } else if (mode == 2) {
        int h  = m0 >> 7;
        int d0 = (m0 & 127) + tx*4;
        float* base = g_v + ((size_t)(b*NKV + h))*SEQ*HD;
        #pragma unroll
        for (int i = 0; i < 4; i++) {
            *(float4*)(base + (size_t)(s0 + ty*4 + i)*HD + d0) =
                make_float4(acc[i][0], acc[i][1], acc[i][2], acc[i][3]);
        }
    } else {
        int h  = m0 >> 7;
        int d0 = (m0 & 127) + tx*4;
        int dh = d0 >> 1;
        float* base = (mode == 0) ? g_q + ((size_t)(b*NH  + h))*SEQ*HD
                                  : g_k + ((size_t)(b*NKV + h))*SEQ*HD;
        #pragma unroll
        for (int i = 0; i < 4; i++) {
            int srow = s0 + ty*4 + i;
            const float* f = freqs + ((size_t)srow*64 + dh)*2;
            float c0 = f[0], n0 = f[1], c1 = f[2], n1 = f[3];
            float e0 = acc[i][0]*n0 - acc[i][1]*c0;
            float o0 = acc[i][0]*c0 + acc[i][1]*n0;
            float e1 = acc[i][2]*n1 - acc[i][3]*c1;
            float o1 = acc[i][2]*c1 + acc[i][3]*n1;
            *(float4*)(base + (size_t)srow*HD + d0) = make_float4(e0, o0, e1, o1);
        }
    }
}

/* =====================================================================
 * k_flash: causal flash attention, 2-term bf16 split, mma m16n8k16.
 *   BM=128, BN=64, 8 warps, warp-local softmax (16 rows/warp).
 *   Smem layouts (32-bit words; each k-pair = [hi-word, lo-word]):
 *     sQ [m=128][jq=64][2]  stride 136 words/row
 *     sK [n= 64][jq=64][2]  stride 136
 *     sV [d=128][pj=32][2]  stride  72  (p-pairs per d row)
 *     sP [m=128][pj=32][2]  stride  72  (aliased by fp32 V staging)
 *   grid (SEQ/128, NH, B); GQA kv head = h>>1; tail-first scheduling.
 * =====================================================================*/
#define QS 136
#define KS 136
#define VS 72
#define PS 72
#define STS_ 132                      /* fp32 V staging stride */
#define SQ_OFF  0
#define SK_OFF  (128*QS)              /* 17408 */
#define SV_OFF  (SK_OFF + 64*KS)      /* 26112 */
#define SP_OFF  (SV_OFF + 128*VS)     /* 35328 */
#define STG_OFF SP_OFF                /* fp32 V staging aliases P */
#define FLASH_WORDS (SP_OFF + 128*PS) /* 44544 */
#define FLASH_SMEM  (FLASH_WORDS * 4) /* 178176 B */

__global__ void __launch_bounds__(256, 1) k_flash()
{
    extern __shared__ uint32_t smw[];
    uint32_t* sQ = smw + SQ_OFF;
    uint32_t* sK = smw + SK_OFF;
    uint32_t* sV = smw + SV_OFF;
    uint32_t* sP = smw + SP_OFF;
    float*    stF = (float*)(smw + STG_OFF);   /* [p=64][d=128] fp32 */

    int tid = threadIdx.x, lane = tid & 31, w = tid >> 5;
    int qt = (int)gridDim.x - 1 - (int)blockIdx.x;     /* heavy tiles first */
    int h = blockIdx.y, b = blockIdx.z;
    int gid = lane >> 2, qd = lane & 3;

    const float* Qg = g_q + ((size_t)(b*NH  + h))     *SEQ*HD + (size_t)qt*128*HD;
    const float* Kb = g_k + ((size_t)(b*NKV + (h>>1)))*SEQ*HD;
    const float* Vb = g_v + ((size_t)(b*NKV + (h>>1)))*SEQ*HD;

    /* ---- load Q tile: scale, split to bf16 hi/lo pairs ---- */
    #pragma unroll
    for (int it = 0; it < 16; it++) {
        int slot = tid + it*256;
        int r = slot >> 5, c4 = (slot & 31) * 4;
        float4 v = *(const float4*)(Qg + (size_t)r*HD + c4);
        uint32_t h01, l01, h23, l23;
        split2(v.x*INV_SQRT_HD, v.y*INV_SQRT_HD, h01, l01);
        split2(v.z*INV_SQRT_HD, v.w*INV_SQRT_HD, h23, l23);
        uint4 pk = make_uint4(h01, l01, h23, l23);
        *(uint4*)(sQ + (size_t)r*QS + c4) = pk;   /* word off = jq*2 = c4 */
    }

    int m0 = w*16;
    float o[16][4] = {};
    float miA = -1e30f, miB = -1e30f, liA = 0.f, liB = 0.f;
    int row_min = qt*128 + w*16;
    int row_max = row_min + 15;
    int nkt = 2*qt + 2;

    for (int kt = 0; kt < nkt; kt++) {
        const float* Kg = Kb + (size_t)kt*64*HD;
        const float* Vg = Vb + (size_t)kt*64*HD;
        /* ---- K: load + split; V: coalesced fp32 stage ---- */
        #pragma unroll
        for (int it = 0; it < 8; it++) {
            int slot = tid + it*256;
            int r = slot >> 5, c4 = (slot & 31) * 4;
            float4 kv = *(const float4*)(Kg + (size_t)r*HD + c4);
            uint32_t h01, l01, h23, l23;
            split2(kv.x, kv.y, h01, l01);
            split2(kv.z, kv.w, h23, l23);
            *(uint4*)(sK + (size_t)r*KS + c4) = make_uint4(h01, l01, h23, l23);
            float4 vv = *(const float4*)(Vg + (size_t)r*HD + c4);
            *(float4*)(stF + (size_t)r*STS_ + c4) = vv;
        }
        __syncthreads();

        /* ---- V transpose-split: stage[p][d] -> sV[d][pj][hi,lo] ----
           d = t & 127 (lane-consecutive -> conflict-free staging reads),
           pj = t >> 7 (constant per warp). 4096 items = 128 d x 32 pj. */
        #pragma unroll
        for (int it = 0; it < 16; it++) {
            int t = tid + it*256;
            int d  = t & 127;
            int pj = t >> 7;
            float f0 = stF[(size_t)(2*pj    )*STS_ + d];
            float f1 = stF[(size_t)(2*pj + 1)*STS_ + d];
            uint32_t hi, lo;
            split2(f0, f1, hi, lo);
            *(uint2*)(sV + (size_t)d*VS + pj*2) = make_uint2(hi, lo);
        }

        bool active = (kt*64 <= row_max);
        float s[8][4] = {};
        if (active) {
            /* ---- S = Q K^T ---- */
            #pragma unroll
            for (int ks = 0; ks < 8; ks++) {
                uint2 qa0 = *(const uint2*)(sQ + (size_t)(m0+gid  )*QS + (8*ks+qd  )*2);
                uint2 qa1 = *(const uint2*)(sQ + (size_t)(m0+gid+8)*QS + (8*ks+qd  )*2);
                uint2 qa2 = *(const uint2*)(sQ + (size_t)(m0+gid  )*QS + (8*ks+qd+4)*2);
                uint2 qa3 = *(const uint2*)(sQ + (size_t)(m0+gid+8)*QS + (8*ks+qd+4)*2);
                uint32_t ah[4] = {qa0.x, qa1.x, qa2.x, qa3.x};
                uint32_t al[4] = {qa0.y, qa1.y, qa2.y, qa3.y};
                #pragma unroll
                for (int nt = 0; nt < 8; nt++) {
                    uint2 kb0 = *(const uint2*)(sK + (size_t)(nt*8+gid)*KS + (8*ks+qd  )*2);
                    uint2 kb1 = *(const uint2*)(sK + (size_t)(nt*8+gid)*KS + (8*ks+qd+4)*2);
                    mma3b(s[nt], ah, al, kb0.x, kb1.x, kb0.y, kb1.y);
                }
            }

            /* ---- causal mask (partial tiles only) ---- */
            if (kt*64 + 63 > row_min) {
                int rA = row_min + gid, rB = rA + 8;
                #pragma unroll
                for (int nt = 0; nt < 8; nt++) {
                    int c0 = kt*64 + nt*8 + 2*qd;
                    if (c0     > rA) s[nt][0] = -1e30f;
                    if (c0 + 1 > rA) s[nt][1] = -1e30f;
                    if (c0     > rB) s[nt][2] = -1e30f;
                    if (c0 + 1 > rB) s[nt][3] = -1e30f;
                }
            }

            /* ---- online softmax (rows A=gid, B=gid+8; 4-lane groups) ---- */
            float mA = -1e30f, mB = -1e30f;
            #pragma unroll
            for (int nt = 0; nt < 8; nt++) {
                mA = fmaxf(mA, fmaxf(s[nt][0], s[nt][1]));
                mB = fmaxf(mB, fmaxf(s[nt][2], s[nt][3]));
            }
            mA = fmaxf(mA, __shfl_xor_sync(0xffffffffu, mA, 1));
            mA = fmaxf(mA, __shfl_xor_sync(0xffffffffu, mA, 2));
            mB = fmaxf(mB, __shfl_xor_sync(0xffffffffu, mB, 1));
            mB = fmaxf(mB, __shfl_xor_sync(0xffffffffu, mB, 2));
            float newmA = fmaxf(miA, mA), newmB = fmaxf(miB, mB);
            float alA = __expf(miA - newmA), alB = __expf(miB - newmB);
            float sumA = 0.f, sumB = 0.f;
            #pragma unroll
            for (int nt = 0; nt < 8; nt++) {
                s[nt][0] = __expf(s[nt][0] - newmA);
                s[nt][1] = __expf(s[nt][1] - newmA);
                s[nt][2] = __expf(s[nt][2] - newmB);
                s[nt][3] = __expf(s[nt][3] - newmB);
                sumA += s[nt][0] + s[nt][1];
                sumB += s[nt][2] + s[nt][3];
            }
            sumA += __shfl_xor_sync(0xffffffffu, sumA, 1);
            sumA += __shfl_xor_sync(0xffffffffu, sumA, 2);
            sumB += __shfl_xor_sync(0xffffffffu, sumB, 1);
            sumB += __shfl_xor_sync(0xffffffffu, sumB, 2);
            liA = liA*alA + sumA;  miA = newmA;
            liB = liB*alB + sumB;  miB = newmB;

            /* ---- rescale O ---- */
            #pragma unroll
            for (int nt = 0; nt < 16; nt++) {
                o[nt][0] *= alA; o[nt][1] *= alA;
                o[nt][2] *= alB; o[nt][3] *= alB;
            }
        }
        /* all transpose-split V reads of the staging region (aliased with
           sP) and QK reads of sK complete before P is stored */
        __syncthreads();

        if (active) {
            /* ---- store P split bf16 (own warp's rows only) ---- */
            #pragma unroll
            for (int nt = 0; nt < 8; nt++) {
                uint32_t hA, lA, hB, lB;
                split2(s[nt][0], s[nt][1], hA, lA);
                split2(s[nt][2], s[nt][3], hB, lB);
                *(uint2*)(sP + (size_t)(m0+gid  )*PS + (nt*4+qd)*2) = make_uint2(hA, lA);
                *(uint2*)(sP + (size_t)(m0+gid+8)*PS + (nt*4+qd)*2) = make_uint2(hB, lB);
            }
            __syncwarp();

            /* ---- O += P V ---- */
            #pragma unroll
            for (int ks = 0; ks < 4; ks++) {
                uint2 pa0 = *(const uint2*)(sP + (size_t)(m0+gid  )*PS + (8*ks+qd  )*2);
                uint2 pa1 = *(const uint2*)(sP + (size_t)(m0+gid+8)*PS + (8*ks+qd  )*2);
                uint2 pa2 = *(const uint2*)(sP + (size_t)(m0+gid  )*PS + (8*ks+qd+4)*2);
                uint2 pa3 = *(const uint2*)(sP + (size_t)(m0+gid+8)*PS + (8*ks+qd+4)*2);
                uint32_t ph[4] = {pa0.x, pa1.x, pa2.x, pa3.x};
                uint32_t pl[4] = {pa0.y, pa1.y, pa2.y, pa3.y};
                #pragma unroll
                for (int nt = 0; nt < 16; nt++) {
                    uint2 vb0 = *(const uint2*)(sV + (size_t)(nt*8+gid)*VS + (8*ks+qd  )*2);
                    uint2 vb1 = *(const uint2*)(sV + (size_t)(nt*8+gid)*VS + (8*ks+qd+4)*2);
                    mma3b(o[nt], ph, pl, vb0.x, vb1.x, vb0.y, vb1.y);
                }
            }
        }
        __syncthreads();
    }

    /* ---- epilogue: O/l -> g_ao [b, s, h*HD + d] ---- */
    float invA = 1.0f / liA, invB = 1.0f / liB;
    float* Og = g_ao + ((size_t)b*SEQ + (size_t)qt*128)*DIM + (size_t)h*HD;
    #pragma unroll
    for (int nt = 0; nt < 16; nt++) {
        int c = nt*8 + 2*qd;
        float2 vA = make_float2(o[nt][0]*invA, o[nt][1]*invA);
        float2 vB = make_float2(o[nt][2]*invB, o[nt][3]*invB);
        *(float2*)(Og + (size_t)(m0 + gid)    *DIM + c) = vA;
        *(float2*)(Og + (size_t)(m0 + gid + 8)*DIM + c) = vB;
    }
}

/* ========================= launch ========================= */
extern "C" void kernel_launch(void* const* d_in, const int* in_sizes, int n_in,
                              void* d_out, int out_size)
{
    const float* x  = (const float*)d_in[0];
    const float* wq = (const float*)d_in[1];
    const float* wk = (const float*)d_in[2];
    const float* wv = (const float*)d_in[3];
    const float* wo = (const float*)d_in[4];
    const float* Sq = (const float*)d_in[5];
    const float* Sk = (const float*)d_in[6];
    const float* Sv = (const float*)d_in[7];
    const float* So = (const float*)d_in[8];
    const float* fr = (const float*)d_in[9];
    float* out = (float*)d_out;

    cudaFuncSetAttribute(k_flash, cudaFuncAttributeMaxDynamicSharedMemorySize,
                         FLASH_SMEM);

    dim3 blk(256);
    /* AS_{q,k,v} = x @ S / 64 */
    k_gemm<<<dim3(32, 3, BATCH), blk>>>(x, Sq, Sk, Sv, So, wq, wk, wv, wo, 0);
    /* T_{q,k,v,o} = w @ S */
    k_gemm<<<dim3(32, 4, BATCH), blk>>>(x, Sq, Sk, Sv, So, wq, wk, wv, wo, 1);
    /* q/k/v projections (+RoPE, layout to [b,h,s,d]) */
    k_proj<<<dim3(32, 32, BATCH), blk>>>(fr, out, 0);
    k_proj<<<dim3(32, 16, BATCH), blk>>>(fr, out, 1);
    k_proj<<<dim3(32, 16, BATCH), blk>>>(fr, out, 2);
    /* causal flash attention (2-term bf16 split, m16n8k16) -> g_ao */
    k_flash<<<dim3(SEQ/128, NH, BATCH), blk, FLASH_SMEM>>>();
    /* AS_o = attn_out @ So / 64 */
    k_gemm<<<dim3(32, 1, BATCH), blk>>>(x, Sq, Sk, Sv, So, wq, wk, wv, wo, 2);
    /* final = AS_o @ To^T -> d_out */
    k_proj<<<dim3(32, 32, BATCH), blk>>>(fr, out, 3);
}